// round 3
// baseline (speedup 1.0000x reference)
#include <cuda_runtime.h>

// Problem shapes (compile-time constants)
#define BATCH 8
#define NC    28
#define HH    256
#define WCC   310
#define WPP   256

static constexpr int HWC = HH * WCC;                 // 79360
static constexpr int HWP = HH * WPP;                 // 65536
static constexpr int NPIX_C = BATCH * HWC;           // 634880  (= 2480 * 256)
static constexpr int NPIX_P = BATCH * HWP;           // 524288  (= 2048 * 256)
static constexpr int XC_ELEMS = BATCH * NC * HWC;    // 17,776,640

// Block-schedule interleave: 16 groups x (155 xc + 128 xp) blocks.
// Each group covers half a batch image in both domains, so the xp path's
// shifted z reads hit the z lines the xc path just pulled into L2.
static constexpr int XC_BLK_PER_GRP = 155;
static constexpr int GRP_BLKS = 283;                 // 155 + 128

__global__ void __launch_bounds__(256, 3)
dp_fused_kernel(const float* __restrict__ z,
                const float* __restrict__ yc,
                const float* __restrict__ phi_c,
                const float* __restrict__ yp,
                const float* __restrict__ phi_p,
                const float* __restrict__ xc_k_1,
                const float* __restrict__ xp_k_1,
                const float* __restrict__ mu,
                const float* __restrict__ mu_c,
                const float* __restrict__ mu_p,
                float* __restrict__ out)
{
    const int g = blockIdx.x / GRP_BLKS;
    const int j = blockIdx.x - g * GRP_BLKS;
    const float mu_ = mu[0];

    // Identity used in both branches (wc + wz = 1, A linear):
    //   out[c] = m[c] + t * phi[c],  m[c] = wA*z[c] + wz*x[c],
    //   t = (y - sum_c m[c]*phi[c]) / denom
    if (j < XC_BLK_PER_GRP) {
        // ---------------- xc update (coded domain, W=310) ----------------
        const int idx = (g * XC_BLK_PER_GRP + j) * 256 + threadIdx.x;  // < NPIX_C
        const float muc = mu_c[0];
        const float inv = 1.f / (mu_ + muc);
        const float wA  = muc * inv;     // weight on z
        const float wz  = mu_ * inv;     // weight on xp_k_1
        const int b   = idx / HWC;
        const int rem = idx - b * HWC;           // h*WC + w
        const int base = b * (NC * HWC) + rem;   // offset of channel 0

        float mr[NC], pr[NC];
        float s = 0.f, am = 0.f;
        #pragma unroll
        for (int c = 0; c < NC; ++c) {
            const int o = base + c * HWC;
            const float zv = z[o];                 // reused later by xp path: keep in L2
            const float pv = __ldcs(&phi_c[o]);    // pure stream
            const float xv = __ldcs(&xp_k_1[o]);   // pure stream
            float m = wA * zv;
            m = fmaf(wz, xv, m);
            mr[c] = m; pr[c] = pv;
            s  = fmaf(pv, pv, s);
            am = fmaf(m,  pv, am);
        }
        if (s == 0.f) s = 1.f;
        const float t = (yc[idx] - am) / (mu_ + muc + s);

        #pragma unroll
        for (int c = 0; c < NC; ++c) {
            __stcs(&out[base + c * HWC], fmaf(t, pr[c], mr[c]));
        }
    } else {
        // ---------------- xp update (PAN domain, W=256) ----------------
        const int jb = g * (GRP_BLKS - XC_BLK_PER_GRP) + (j - XC_BLK_PER_GRP);
        const int jj = jb * 256 + threadIdx.x;   // < NPIX_P
        const float mup = mu_p[0];
        const float inv = 1.f / (mu_ + mup);
        const float wA  = mup * inv;     // weight on z_shiftback
        const float wz  = mu_ * inv;     // weight on xc_k_1
        const int b   = jj / HWP;
        const int rem = jj - b * HWP;            // h*WP + w
        const int h   = rem >> 8;                // WP = 256
        const int w   = rem & 255;
        const int basep = b * (NC * HWP) + rem;                  // phi_p / xc_k_1 / out
        const int basec = b * (NC * HWC) + h * WCC + w;          // z (shifted-back read)

        float mr[NC], pr[NC];
        float s = 0.f, am = 0.f;
        #pragma unroll
        for (int c = 0; c < NC; ++c) {
            // shift_back: z[b,c,h,(w+2c)%310]; w<=255, c<=27 -> w+2c<=309, no wrap
            const float zv = z[basec + c * HWC + 2 * c];
            const int  o  = basep + c * HWP;
            const float pv = __ldcs(&phi_p[o]);
            const float xv = __ldcs(&xc_k_1[o]);
            float m = wA * zv;
            m = fmaf(wz, xv, m);
            mr[c] = m; pr[c] = pv;
            s  = fmaf(pv, pv, s);
            am = fmaf(m,  pv, am);
        }
        if (s == 0.f) s = 1.f;
        const float t = (yp[jj] - am) / (mu_ + mup + s);

        float* __restrict__ outp = out + XC_ELEMS;
        #pragma unroll
        for (int c = 0; c < NC; ++c) {
            __stcs(&outp[basep + c * HWP], fmaf(t, pr[c], mr[c]));
        }
    }
}

extern "C" void kernel_launch(void* const* d_in, const int* in_sizes, int n_in,
                              void* d_out, int out_size)
{
    const float* z      = (const float*)d_in[0];
    const float* yc     = (const float*)d_in[1];
    const float* phi_c  = (const float*)d_in[2];
    const float* yp     = (const float*)d_in[3];
    const float* phi_p  = (const float*)d_in[4];
    const float* xc_k_1 = (const float*)d_in[5];
    const float* xp_k_1 = (const float*)d_in[6];
    const float* mu     = (const float*)d_in[7];
    const float* mu_c   = (const float*)d_in[8];
    const float* mu_p   = (const float*)d_in[9];
    float* out = (float*)d_out;

    const int blocks = (NPIX_C + NPIX_P) / 256;   // 4528 = 16 * 283
    dp_fused_kernel<<<blocks, 256>>>(z, yc, phi_c, yp, phi_p,
                                     xc_k_1, xp_k_1, mu, mu_c, mu_p, out);
}

// round 4
// speedup vs baseline: 1.0093x; 1.0093x over previous
#include <cuda_runtime.h>

// Problem shapes (compile-time constants)
#define BATCH 8
#define NC    28
#define HH    256
#define WCC   310
#define WPP   256

static constexpr int HWC = HH * WCC;                 // 79360
static constexpr int HWP = HH * WPP;                 // 65536
static constexpr int NPIX_C = BATCH * HWC;           // 634880  (= 2480 * 256)
static constexpr int NPIX_P = BATCH * HWP;           // 524288  (= 2048 * 256)
static constexpr int XC_ELEMS = BATCH * NC * HWC;    // 17,776,640

// Block-schedule interleave: 16 groups x (155 xc + 128 xp) blocks.
// Each group covers half a batch image in both domains, so the xp path's
// shifted z reads hit the z lines the xc path just pulled into L2.
static constexpr int XC_BLK_PER_GRP = 155;
static constexpr int GRP_BLKS = 283;                 // 155 + 128

__global__ void __launch_bounds__(256, 3)
dp_fused_kernel(const float* __restrict__ z,
                const float* __restrict__ yc,
                const float* __restrict__ phi_c,
                const float* __restrict__ yp,
                const float* __restrict__ phi_p,
                const float* __restrict__ xc_k_1,
                const float* __restrict__ xp_k_1,
                const float* __restrict__ mu,
                const float* __restrict__ mu_c,
                const float* __restrict__ mu_p,
                float* __restrict__ out)
{
    const int g = blockIdx.x / GRP_BLKS;
    const int j = blockIdx.x - g * GRP_BLKS;
    const float mu_ = mu[0];

    // Identity used in both branches (wc + wz = 1, A linear):
    //   out[c] = m[c] + t * phi[c],  m[c] = wA*z[c] + wz*x[c],
    //   t = (y - sum_c m[c]*phi[c]) / denom
    if (j < XC_BLK_PER_GRP) {
        // ---------------- xc update (coded domain, W=310) ----------------
        const int idx = (g * XC_BLK_PER_GRP + j) * 256 + threadIdx.x;  // < NPIX_C
        const float muc = mu_c[0];
        const float inv = 1.f / (mu_ + muc);
        const float wA  = muc * inv;     // weight on z
        const float wz  = mu_ * inv;     // weight on xp_k_1
        const int b   = idx / HWC;
        const int rem = idx - b * HWC;           // h*WC + w
        const int base = b * (NC * HWC) + rem;   // offset of channel 0

        float mr[NC], pr[NC];
        float s = 0.f, am = 0.f;
        #pragma unroll
        for (int c = 0; c < NC; ++c) {
            const int o = base + c * HWC;
            const float zv = z[o];                 // reused later by xp path: keep in L2
            const float pv = __ldcs(&phi_c[o]);    // pure stream
            const float xv = __ldcs(&xp_k_1[o]);   // pure stream
            float m = wA * zv;
            m = fmaf(wz, xv, m);
            mr[c] = m; pr[c] = pv;
            s  = fmaf(pv, pv, s);
            am = fmaf(m,  pv, am);
        }
        if (s == 0.f) s = 1.f;
        const float t = (yc[idx] - am) / (mu_ + muc + s);

        #pragma unroll
        for (int c = 0; c < NC; ++c) {
            out[base + c * HWC] = fmaf(t, pr[c], mr[c]);
        }
    } else {
        // ---------------- xp update (PAN domain, W=256) ----------------
        const int jb = g * (GRP_BLKS - XC_BLK_PER_GRP) + (j - XC_BLK_PER_GRP);
        const int jj = jb * 256 + threadIdx.x;   // < NPIX_P
        const float mup = mu_p[0];
        const float inv = 1.f / (mu_ + mup);
        const float wA  = mup * inv;     // weight on z_shiftback
        const float wz  = mu_ * inv;     // weight on xc_k_1
        const int b   = jj / HWP;
        const int rem = jj - b * HWP;            // h*WP + w
        const int h   = rem >> 8;                // WP = 256
        const int w   = rem & 255;
        const int basep = b * (NC * HWP) + rem;                  // phi_p / xc_k_1 / out
        const int basec = b * (NC * HWC) + h * WCC + w;          // z (shifted-back read)

        float mr[NC], pr[NC];
        float s = 0.f, am = 0.f;
        #pragma unroll
        for (int c = 0; c < NC; ++c) {
            // shift_back: z[b,c,h,(w+2c)%310]; w<=255, c<=27 -> w+2c<=309, no wrap
            const float zv = z[basec + c * HWC + 2 * c];
            const int  o  = basep + c * HWP;
            const float pv = __ldcs(&phi_p[o]);
            const float xv = __ldcs(&xc_k_1[o]);
            float m = wA * zv;
            m = fmaf(wz, xv, m);
            mr[c] = m; pr[c] = pv;
            s  = fmaf(pv, pv, s);
            am = fmaf(m,  pv, am);
        }
        if (s == 0.f) s = 1.f;
        const float t = (yp[jj] - am) / (mu_ + mup + s);

        float* __restrict__ outp = out + XC_ELEMS;
        #pragma unroll
        for (int c = 0; c < NC; ++c) {
            outp[basep + c * HWP] = fmaf(t, pr[c], mr[c]);
        }
    }
}

extern "C" void kernel_launch(void* const* d_in, const int* in_sizes, int n_in,
                              void* d_out, int out_size)
{
    const float* z      = (const float*)d_in[0];
    const float* yc     = (const float*)d_in[1];
    const float* phi_c  = (const float*)d_in[2];
    const float* yp     = (const float*)d_in[3];
    const float* phi_p  = (const float*)d_in[4];
    const float* xc_k_1 = (const float*)d_in[5];
    const float* xp_k_1 = (const float*)d_in[6];
    const float* mu     = (const float*)d_in[7];
    const float* mu_c   = (const float*)d_in[8];
    const float* mu_p   = (const float*)d_in[9];
    float* out = (float*)d_out;

    const int blocks = (NPIX_C + NPIX_P) / 256;   // 4528 = 16 * 283
    dp_fused_kernel<<<blocks, 256>>>(z, yc, phi_c, yp, phi_p,
                                     xc_k_1, xp_k_1, mu, mu_c, mu_p, out);
}

// round 5
// speedup vs baseline: 1.0293x; 1.0198x over previous
#include <cuda_runtime.h>

// Problem shapes (compile-time constants)
#define BATCH 8
#define NC    28
#define HH    256
#define WCC   310
#define WPP   256

static constexpr int HWC = HH * WCC;                 // 79360
static constexpr int HWP = HH * WPP;                 // 65536
static constexpr int NPIX_C = BATCH * HWC;           // 634880  (= 2480 * 256)
static constexpr int NPIX_P = BATCH * HWP;           // 524288  (= 2048 * 256)
static constexpr int XC_ELEMS = BATCH * NC * HWC;    // 17,776,640

// Block-schedule interleave: 16 groups x (155 xc + 128 xp) blocks.
// Each group covers half a batch image in both domains, so the xp path's
// shifted z reads hit the z lines the xc path just pulled into L2.
static constexpr int XC_BLK_PER_GRP = 155;
static constexpr int GRP_BLKS = 283;                 // 155 + 128

__global__ void __launch_bounds__(256, 3)
dp_fused_kernel(const float* __restrict__ z,
                const float* __restrict__ yc,
                const float* __restrict__ phi_c,
                const float* __restrict__ yp,
                const float* __restrict__ phi_p,
                const float* __restrict__ xc_k_1,
                const float* __restrict__ xp_k_1,
                const float* __restrict__ mu,
                const float* __restrict__ mu_c,
                const float* __restrict__ mu_p,
                float* __restrict__ out)
{
    const int g = blockIdx.x / GRP_BLKS;
    const int j = blockIdx.x - g * GRP_BLKS;
    const float mu_ = mu[0];

    // Identity used in both branches (wc + wz = 1, A linear):
    //   out[c] = m[c] + t * phi[c],  m[c] = wA*z[c] + wz*x[c],
    //   t = (y - sum_c m[c]*phi[c]) / denom
    if (j < XC_BLK_PER_GRP) {
        // ---------------- xc update (coded domain, W=310) ----------------
        const int idx = (g * XC_BLK_PER_GRP + j) * 256 + threadIdx.x;  // < NPIX_C
        const float muc = mu_c[0];
        const float inv = 1.f / (mu_ + muc);
        const float wA  = muc * inv;     // weight on z
        const float wz  = mu_ * inv;     // weight on xp_k_1
        const int b   = idx / HWC;
        const int rem = idx - b * HWC;           // h*WC + w
        const int base = b * (NC * HWC) + rem;   // offset of channel 0

        float mr[NC], pr[NC];
        float s = 0.f, am = 0.f;
        #pragma unroll
        for (int c = 0; c < NC; ++c) {
            const int o = base + c * HWC;
            const float zv = z[o];
            const float pv = phi_c[o];
            const float xv = xp_k_1[o];
            float m = wA * zv;
            m = fmaf(wz, xv, m);
            mr[c] = m; pr[c] = pv;
            s  = fmaf(pv, pv, s);
            am = fmaf(m,  pv, am);
        }
        if (s == 0.f) s = 1.f;
        const float t = (yc[idx] - am) / (mu_ + muc + s);

        #pragma unroll
        for (int c = 0; c < NC; ++c) {
            out[base + c * HWC] = fmaf(t, pr[c], mr[c]);
        }
    } else {
        // ---------------- xp update (PAN domain, W=256) ----------------
        const int jb = g * (GRP_BLKS - XC_BLK_PER_GRP) + (j - XC_BLK_PER_GRP);
        const int jj = jb * 256 + threadIdx.x;   // < NPIX_P
        const float mup = mu_p[0];
        const float inv = 1.f / (mu_ + mup);
        const float wA  = mup * inv;     // weight on z_shiftback
        const float wz  = mu_ * inv;     // weight on xc_k_1
        const int b   = jj / HWP;
        const int rem = jj - b * HWP;            // h*WP + w
        const int h   = rem >> 8;                // WP = 256
        const int w   = rem & 255;
        const int basep = b * (NC * HWP) + rem;                  // phi_p / xc_k_1 / out
        const int basec = b * (NC * HWC) + h * WCC + w;          // z (shifted-back read)

        float mr[NC], pr[NC];
        float s = 0.f, am = 0.f;
        #pragma unroll
        for (int c = 0; c < NC; ++c) {
            // shift_back: z[b,c,h,(w+2c)%310]; w<=255, c<=27 -> w+2c<=309, no wrap
            const float zv = z[basec + c * HWC + 2 * c];
            const int  o  = basep + c * HWP;
            const float pv = phi_p[o];
            const float xv = xc_k_1[o];
            float m = wA * zv;
            m = fmaf(wz, xv, m);
            mr[c] = m; pr[c] = pv;
            s  = fmaf(pv, pv, s);
            am = fmaf(m,  pv, am);
        }
        if (s == 0.f) s = 1.f;
        const float t = (yp[jj] - am) / (mu_ + mup + s);

        float* __restrict__ outp = out + XC_ELEMS;
        #pragma unroll
        for (int c = 0; c < NC; ++c) {
            outp[basep + c * HWP] = fmaf(t, pr[c], mr[c]);
        }
    }
}

extern "C" void kernel_launch(void* const* d_in, const int* in_sizes, int n_in,
                              void* d_out, int out_size)
{
    const float* z      = (const float*)d_in[0];
    const float* yc     = (const float*)d_in[1];
    const float* phi_c  = (const float*)d_in[2];
    const float* yp     = (const float*)d_in[3];
    const float* phi_p  = (const float*)d_in[4];
    const float* xc_k_1 = (const float*)d_in[5];
    const float* xp_k_1 = (const float*)d_in[6];
    const float* mu     = (const float*)d_in[7];
    const float* mu_c   = (const float*)d_in[8];
    const float* mu_p   = (const float*)d_in[9];
    float* out = (float*)d_out;

    const int blocks = (NPIX_C + NPIX_P) / 256;   // 4528 = 16 * 283
    dp_fused_kernel<<<blocks, 256>>>(z, yc, phi_c, yp, phi_p,
                                     xc_k_1, xp_k_1, mu, mu_c, mu_p, out);
}

// round 6
// speedup vs baseline: 1.0315x; 1.0022x over previous
#include <cuda_runtime.h>

// Problem shapes (compile-time constants)
#define BATCH 8
#define NC    28
#define HH    256
#define WCC   310
#define WPP   256

static constexpr int HWC = HH * WCC;                 // 79360
static constexpr int HWP = HH * WPP;                 // 65536
static constexpr int NPIX_C = BATCH * HWC;           // 634880  (= 2480 * 256)
static constexpr int NPIX_P = BATCH * HWP;           // 524288  (= 2048 * 256)
static constexpr int XC_ELEMS = BATCH * NC * HWC;    // 17,776,640

// Block-schedule interleave: 16 groups x (155 xc + 128 xp) blocks.
// Each group covers half a batch image in both domains, so the xp path's
// shifted z reads hit the z lines the xc path just pulled into L2.
static constexpr int XC_BLK_PER_GRP = 155;
static constexpr int GRP_BLKS = 283;                 // 155 + 128

// Occupancy deliberately capped at 2 CTAs/SM: with ~56 front-batched LDGs
// per thread, 3+ co-resident CTAs oversubscribe the per-SM L1tex wavefront
// queue and LOWER achieved DRAM bandwidth (measured R1..R5 trend).
__global__ void __launch_bounds__(256, 2)
dp_fused_kernel(const float* __restrict__ z,
                const float* __restrict__ yc,
                const float* __restrict__ phi_c,
                const float* __restrict__ yp,
                const float* __restrict__ phi_p,
                const float* __restrict__ xc_k_1,
                const float* __restrict__ xp_k_1,
                const float* __restrict__ mu,
                const float* __restrict__ mu_c,
                const float* __restrict__ mu_p,
                float* __restrict__ out)
{
    const int g = blockIdx.x / GRP_BLKS;
    const int j = blockIdx.x - g * GRP_BLKS;
    const float mu_ = mu[0];

    // Identity used in both branches (wc + wz = 1, A linear):
    //   out[c] = m[c] + t * phi[c],  m[c] = wA*z[c] + wz*x[c],
    //   t = (y - sum_c m[c]*phi[c]) / denom
    if (j < XC_BLK_PER_GRP) {
        // ---------------- xc update (coded domain, W=310) ----------------
        const int idx = (g * XC_BLK_PER_GRP + j) * 256 + threadIdx.x;  // < NPIX_C
        const float muc = mu_c[0];
        const float inv = 1.f / (mu_ + muc);
        const float wA  = muc * inv;     // weight on z
        const float wz  = mu_ * inv;     // weight on xp_k_1
        const int b   = idx / HWC;
        const int rem = idx - b * HWC;           // h*WC + w
        const int base = b * (NC * HWC) + rem;   // offset of channel 0

        float mr[NC], pr[NC];
        float s = 0.f, am = 0.f;
        #pragma unroll
        for (int c = 0; c < NC; ++c) {
            const int o = base + c * HWC;
            const float zv = z[o];
            const float pv = phi_c[o];
            const float xv = xp_k_1[o];
            float m = wA * zv;
            m = fmaf(wz, xv, m);
            mr[c] = m; pr[c] = pv;
            s  = fmaf(pv, pv, s);
            am = fmaf(m,  pv, am);
        }
        if (s == 0.f) s = 1.f;
        const float t = (yc[idx] - am) / (mu_ + muc + s);

        #pragma unroll
        for (int c = 0; c < NC; ++c) {
            out[base + c * HWC] = fmaf(t, pr[c], mr[c]);
        }
    } else {
        // ---------------- xp update (PAN domain, W=256) ----------------
        const int jb = g * (GRP_BLKS - XC_BLK_PER_GRP) + (j - XC_BLK_PER_GRP);
        const int jj = jb * 256 + threadIdx.x;   // < NPIX_P
        const float mup = mu_p[0];
        const float inv = 1.f / (mu_ + mup);
        const float wA  = mup * inv;     // weight on z_shiftback
        const float wz  = mu_ * inv;     // weight on xc_k_1
        const int b   = jj / HWP;
        const int rem = jj - b * HWP;            // h*WP + w
        const int h   = rem >> 8;                // WP = 256
        const int w   = rem & 255;
        const int basep = b * (NC * HWP) + rem;                  // phi_p / xc_k_1 / out
        const int basec = b * (NC * HWC) + h * WCC + w;          // z (shifted-back read)

        float mr[NC], pr[NC];
        float s = 0.f, am = 0.f;
        #pragma unroll
        for (int c = 0; c < NC; ++c) {
            // shift_back: z[b,c,h,(w+2c)%310]; w<=255, c<=27 -> w+2c<=309, no wrap
            const float zv = z[basec + c * HWC + 2 * c];
            const int  o  = basep + c * HWP;
            const float pv = phi_p[o];
            const float xv = xc_k_1[o];
            float m = wA * zv;
            m = fmaf(wz, xv, m);
            mr[c] = m; pr[c] = pv;
            s  = fmaf(pv, pv, s);
            am = fmaf(m,  pv, am);
        }
        if (s == 0.f) s = 1.f;
        const float t = (yp[jj] - am) / (mu_ + mup + s);

        float* __restrict__ outp = out + XC_ELEMS;
        #pragma unroll
        for (int c = 0; c < NC; ++c) {
            outp[basep + c * HWP] = fmaf(t, pr[c], mr[c]);
        }
    }
}

extern "C" void kernel_launch(void* const* d_in, const int* in_sizes, int n_in,
                              void* d_out, int out_size)
{
    const float* z      = (const float*)d_in[0];
    const float* yc     = (const float*)d_in[1];
    const float* phi_c  = (const float*)d_in[2];
    const float* yp     = (const float*)d_in[3];
    const float* phi_p  = (const float*)d_in[4];
    const float* xc_k_1 = (const float*)d_in[5];
    const float* xp_k_1 = (const float*)d_in[6];
    const float* mu     = (const float*)d_in[7];
    const float* mu_c   = (const float*)d_in[8];
    const float* mu_p   = (const float*)d_in[9];
    float* out = (float*)d_out;

    const int blocks = (NPIX_C + NPIX_P) / 256;   // 4528 = 16 * 283
    dp_fused_kernel<<<blocks, 256>>>(z, yc, phi_c, yp, phi_p,
                                     xc_k_1, xp_k_1, mu, mu_c, mu_p, out);
}

// round 7
// speedup vs baseline: 1.0913x; 1.0580x over previous
#include <cuda_runtime.h>

// Problem shapes (compile-time constants)
#define BATCH 8
#define NC    28
#define HH    256
#define WCC   310
#define WPP   256

static constexpr int HWC = HH * WCC;                 // 79360 (even, %4==0)
static constexpr int HWP = HH * WPP;                 // 65536
static constexpr int NPIX_C = BATCH * HWC;           // 634880
static constexpr int NPIX_P = BATCH * HWP;           // 524288
static constexpr int XC_ELEMS = BATCH * NC * HWC;    // 17,776,640

// float2 path: each thread handles 2 adjacent pixels -> 128-thread blocks
// cover 256 pixels, so block counts match R2 exactly:
//   xc: 634880/256 = 2480 = 16*155,  xp: 524288/256 = 2048 = 16*128
// Interleave: 16 groups x (155 xc + 128 xp); each group covers half a batch
// image in both domains so xp's shifted z reads hit L2.
static constexpr int XC_BLK_PER_GRP = 155;
static constexpr int GRP_BLKS = 283;

__global__ void __launch_bounds__(128, 3)
dp_fused_kernel(const float* __restrict__ z,
                const float* __restrict__ yc,
                const float* __restrict__ phi_c,
                const float* __restrict__ yp,
                const float* __restrict__ phi_p,
                const float* __restrict__ xc_k_1,
                const float* __restrict__ xp_k_1,
                const float* __restrict__ mu,
                const float* __restrict__ mu_c,
                const float* __restrict__ mu_p,
                float* __restrict__ out)
{
    const int g = blockIdx.x / GRP_BLKS;
    const int j = blockIdx.x - g * GRP_BLKS;
    const float mu_ = mu[0];

    // out[c] = m[c] + t*phi[c],  m[c] = wA*z[c] + wz*x[c],
    // t = (y - sum_c m[c]*phi[c]) / (mu + mu_x + sum_c phi[c]^2)
    if (j < XC_BLK_PER_GRP) {
        // ---------------- xc update (coded domain, W=310) ----------------
        // pixel pair index: 2 pixels per thread, consecutive in w
        const int pix = ((g * XC_BLK_PER_GRP + j) * 128 + threadIdx.x) * 2; // even, < NPIX_C
        const float muc = mu_c[0];
        const float inv = 1.f / (mu_ + muc);
        const float wA  = muc * inv;
        const float wz  = mu_ * inv;
        const int b    = pix / HWC;
        const int rem  = pix - b * HWC;          // even
        const int base = b * (NC * HWC) + rem;   // even -> 8B aligned

        float2 mr[NC], pr[NC];
        float2 s  = make_float2(0.f, 0.f);
        float2 am = make_float2(0.f, 0.f);
        #pragma unroll
        for (int c = 0; c < NC; ++c) {
            const int o = base + c * HWC;
            const float2 zv = *(const float2*)(z      + o);
            const float2 pv = *(const float2*)(phi_c  + o);
            const float2 xv = *(const float2*)(xp_k_1 + o);
            float2 m;
            m.x = fmaf(wz, xv.x, wA * zv.x);
            m.y = fmaf(wz, xv.y, wA * zv.y);
            mr[c] = m; pr[c] = pv;
            s.x  = fmaf(pv.x, pv.x, s.x);
            s.y  = fmaf(pv.y, pv.y, s.y);
            am.x = fmaf(m.x, pv.x, am.x);
            am.y = fmaf(m.y, pv.y, am.y);
        }
        if (s.x == 0.f) s.x = 1.f;
        if (s.y == 0.f) s.y = 1.f;
        const float2 y2 = *(const float2*)(yc + pix);
        float2 t;
        t.x = (y2.x - am.x) / (mu_ + muc + s.x);
        t.y = (y2.y - am.y) / (mu_ + muc + s.y);

        #pragma unroll
        for (int c = 0; c < NC; ++c) {
            float2 o2;
            o2.x = fmaf(t.x, pr[c].x, mr[c].x);
            o2.y = fmaf(t.y, pr[c].y, mr[c].y);
            *(float2*)(out + base + c * HWC) = o2;
        }
    } else {
        // ---------------- xp update (PAN domain, W=256) ----------------
        const int jb  = g * (GRP_BLKS - XC_BLK_PER_GRP) + (j - XC_BLK_PER_GRP);
        const int pix = (jb * 128 + threadIdx.x) * 2;   // even, < NPIX_P
        const float mup = mu_p[0];
        const float inv = 1.f / (mu_ + mup);
        const float wA  = mup * inv;
        const float wz  = mu_ * inv;
        const int b   = pix / HWP;
        const int rem = pix - b * HWP;           // even
        const int h   = rem >> 8;                // WP = 256
        const int w   = rem & 255;               // even
        const int basep = b * (NC * HWP) + rem;                 // phi_p / xc_k_1 / out
        const int basec = b * (NC * HWC) + h * WCC + w;         // z (shifted read), even

        float2 mr[NC], pr[NC];
        float2 s  = make_float2(0.f, 0.f);
        float2 am = make_float2(0.f, 0.f);
        #pragma unroll
        for (int c = 0; c < NC; ++c) {
            // shift_back: z[b,c,h,w+2c] and z[b,c,h,w+1+2c]; w+1+2c <= 309, no wrap.
            // offset even -> 8B-aligned float2 load.
            const float2 zv = *(const float2*)(z + basec + c * HWC + 2 * c);
            const int  o  = basep + c * HWP;
            const float2 pv = *(const float2*)(phi_p  + o);
            const float2 xv = *(const float2*)(xc_k_1 + o);
            float2 m;
            m.x = fmaf(wz, xv.x, wA * zv.x);
            m.y = fmaf(wz, xv.y, wA * zv.y);
            mr[c] = m; pr[c] = pv;
            s.x  = fmaf(pv.x, pv.x, s.x);
            s.y  = fmaf(pv.y, pv.y, s.y);
            am.x = fmaf(m.x, pv.x, am.x);
            am.y = fmaf(m.y, pv.y, am.y);
        }
        if (s.x == 0.f) s.x = 1.f;
        if (s.y == 0.f) s.y = 1.f;
        const float2 y2 = *(const float2*)(yp + pix);
        float2 t;
        t.x = (y2.x - am.x) / (mu_ + mup + s.x);
        t.y = (y2.y - am.y) / (mu_ + mup + s.y);

        float* __restrict__ outp = out + XC_ELEMS;
        #pragma unroll
        for (int c = 0; c < NC; ++c) {
            float2 o2;
            o2.x = fmaf(t.x, pr[c].x, mr[c].x);
            o2.y = fmaf(t.y, pr[c].y, mr[c].y);
            *(float2*)(outp + basep + c * HWP) = o2;
        }
    }
}

extern "C" void kernel_launch(void* const* d_in, const int* in_sizes, int n_in,
                              void* d_out, int out_size)
{
    const float* z      = (const float*)d_in[0];
    const float* yc     = (const float*)d_in[1];
    const float* phi_c  = (const float*)d_in[2];
    const float* yp     = (const float*)d_in[3];
    const float* phi_p  = (const float*)d_in[4];
    const float* xc_k_1 = (const float*)d_in[5];
    const float* xp_k_1 = (const float*)d_in[6];
    const float* mu     = (const float*)d_in[7];
    const float* mu_c   = (const float*)d_in[8];
    const float* mu_p   = (const float*)d_in[9];
    float* out = (float*)d_out;

    const int blocks = (NPIX_C + NPIX_P) / 256;   // 4528 = 16 * 283 (128 thr x 2 pix)
    dp_fused_kernel<<<blocks, 128>>>(z, yc, phi_c, yp, phi_p,
                                     xc_k_1, xp_k_1, mu, mu_c, mu_p, out);
}